// round 1
// baseline (speedup 1.0000x reference)
#include <cuda_runtime.h>

#define N_NODES   50000
#define N_EDGES   550000
#define HID       128
#define OUT_CH    64
#define N_GRAPHS  64
#define NEG_SLOPE 0.2f

// ---------------- device scratch (no allocations allowed) ----------------
__device__ float g_h [N_NODES * HID];   // current node features
__device__ float g_hw[N_NODES * HID];   // h @ W
__device__ float g_ssrc[N_NODES];
__device__ float g_sdst[N_NODES];
__device__ int   g_cnt [N_NODES];
__device__ int   g_fill[N_NODES];
__device__ int   g_off [N_NODES + 1];
__device__ int   g_csrc[N_EDGES];       // CSR (by dst) of source node ids
__device__ int   g_gstart[N_GRAPHS + 1];
__device__ float g_pool[N_GRAPHS * HID];

// ---------------- CSR build ----------------
__global__ void k_zero() {
    int i = blockIdx.x * blockDim.x + threadIdx.x;
    if (i < N_NODES) { g_cnt[i] = 0; g_fill[i] = 0; }
}

__global__ void k_hist(const int* __restrict__ dst) {
    for (int i = blockIdx.x * blockDim.x + threadIdx.x; i < N_EDGES;
         i += gridDim.x * blockDim.x)
        atomicAdd(&g_cnt[dst[i]], 1);
}

// single-block exclusive scan of g_cnt -> g_off (50001 entries)
__global__ void k_scan() {
    __shared__ int part[1024];
    const int t  = threadIdx.x;
    const int CH = (N_NODES + 1023) / 1024;   // 49
    int base = t * CH;
    int s = 0;
    for (int i = 0; i < CH; i++) {
        int idx = base + i;
        if (idx < N_NODES) s += g_cnt[idx];
    }
    part[t] = s;
    __syncthreads();
    for (int d = 1; d < 1024; d <<= 1) {
        int v = (t >= d) ? part[t - d] : 0;
        __syncthreads();
        part[t] += v;
        __syncthreads();
    }
    int run = (t == 0) ? 0 : part[t - 1];
    for (int i = 0; i < CH; i++) {
        int idx = base + i;
        if (idx < N_NODES) { g_off[idx] = run; run += g_cnt[idx]; }
    }
    if (t == 1023) g_off[N_NODES] = part[1023];
}

__global__ void k_fillcsr(const int* __restrict__ src, const int* __restrict__ dst) {
    for (int i = blockIdx.x * blockDim.x + threadIdx.x; i < N_EDGES;
         i += gridDim.x * blockDim.x) {
        int d = dst[i];
        int pos = g_off[d] + atomicAdd(&g_fill[d], 1);
        g_csrc[pos] = src[i];
    }
}

// ---------------- embedding gather ----------------
__global__ void k_embed(const int* __restrict__ x, const float* __restrict__ emb) {
    int i = blockIdx.x * blockDim.x + threadIdx.x;      // over N_NODES*32 float4s
    if (i >= N_NODES * 32) return;
    int node = i >> 5, lane = i & 31;
    ((float4*)g_h)[i] = ((const float4*)emb)[x[node] * 32 + lane];
}

// ---------------- GEMM: g_hw = g_h @ W  (50000x128 * 128x128) ----------------
// block: 256 threads, computes 64 rows x 128 cols. Thread tile 4x8 (two float4 col groups).
#define GEMM_SMEM ((64 * 132 + 128 * 128) * 4)
__global__ void k_gemm(const float* __restrict__ W) {
    extern __shared__ float sm[];
    float*  As  = sm;                       // 64 x 132 (padded)
    float4* Ws4 = (float4*)(sm + 64 * 132); // 128 x 32 float4

    const int tid = threadIdx.x;
    const int ct  = tid & 15;       // col group 0..15
    const int rt  = tid >> 4;       // row group 0..15
    const int rowbase = blockIdx.x * 64;

    // load W tile (whole 128x128)
    const float4* Wg4 = (const float4*)W;
#pragma unroll
    for (int j = 0; j < 16; j++) {
        int idx = tid + j * 256;
        Ws4[idx] = Wg4[idx];
    }
    // load A tile (64 rows)
    const float4* Ag4 = (const float4*)g_h;
#pragma unroll
    for (int j = 0; j < 8; j++) {
        int idx = tid + j * 256;          // 2048 float4s
        int r   = idx >> 5;
        int c4  = idx & 31;
        int grow = rowbase + r;
        float4 v = (grow < N_NODES) ? Ag4[grow * 32 + c4]
                                    : make_float4(0.f, 0.f, 0.f, 0.f);
        *(float4*)&As[r * 132 + c4 * 4] = v;
    }
    __syncthreads();

    float acc[4][8];
#pragma unroll
    for (int i = 0; i < 4; i++)
#pragma unroll
        for (int j = 0; j < 8; j++) acc[i][j] = 0.f;

    const int r0 = rt * 4;
#pragma unroll 4
    for (int k = 0; k < 128; k++) {
        float a0 = As[(r0 + 0) * 132 + k];
        float a1 = As[(r0 + 1) * 132 + k];
        float a2 = As[(r0 + 2) * 132 + k];
        float a3 = As[(r0 + 3) * 132 + k];
        float4 b0 = Ws4[k * 32 + ct];
        float4 b1 = Ws4[k * 32 + 16 + ct];
        acc[0][0] += a0 * b0.x; acc[0][1] += a0 * b0.y; acc[0][2] += a0 * b0.z; acc[0][3] += a0 * b0.w;
        acc[0][4] += a0 * b1.x; acc[0][5] += a0 * b1.y; acc[0][6] += a0 * b1.z; acc[0][7] += a0 * b1.w;
        acc[1][0] += a1 * b0.x; acc[1][1] += a1 * b0.y; acc[1][2] += a1 * b0.z; acc[1][3] += a1 * b0.w;
        acc[1][4] += a1 * b1.x; acc[1][5] += a1 * b1.y; acc[1][6] += a1 * b1.z; acc[1][7] += a1 * b1.w;
        acc[2][0] += a2 * b0.x; acc[2][1] += a2 * b0.y; acc[2][2] += a2 * b0.z; acc[2][3] += a2 * b0.w;
        acc[2][4] += a2 * b1.x; acc[2][5] += a2 * b1.y; acc[2][6] += a2 * b1.z; acc[2][7] += a2 * b1.w;
        acc[3][0] += a3 * b0.x; acc[3][1] += a3 * b0.y; acc[3][2] += a3 * b0.z; acc[3][3] += a3 * b0.w;
        acc[3][4] += a3 * b1.x; acc[3][5] += a3 * b1.y; acc[3][6] += a3 * b1.z; acc[3][7] += a3 * b1.w;
    }

    float4* C4 = (float4*)g_hw;
#pragma unroll
    for (int i = 0; i < 4; i++) {
        int row = rowbase + r0 + i;
        if (row < N_NODES) {
            float4 v0 = make_float4(acc[i][0], acc[i][1], acc[i][2], acc[i][3]);
            float4 v1 = make_float4(acc[i][4], acc[i][5], acc[i][6], acc[i][7]);
            C4[row * 32 + ct]      = v0;
            C4[row * 32 + 16 + ct] = v1;
        }
    }
}

// ---------------- attention scalar scores: s_src = hW·a_src, s_dst = hW·a_dst ----------------
__global__ void k_scores(const float* __restrict__ asrc, const float* __restrict__ adst) {
    int gw   = (blockIdx.x * blockDim.x + threadIdx.x) >> 5;
    int lane = threadIdx.x & 31;
    if (gw >= N_NODES) return;
    float4 v = ((const float4*)g_hw)[gw * 32 + lane];
    float4 a = ((const float4*)asrc)[lane];
    float4 d = ((const float4*)adst)[lane];
    float s1 = v.x * a.x + v.y * a.y + v.z * a.z + v.w * a.w;
    float s2 = v.x * d.x + v.y * d.y + v.z * d.z + v.w * d.w;
#pragma unroll
    for (int off = 16; off > 0; off >>= 1) {
        s1 += __shfl_xor_sync(0xffffffffu, s1, off);
        s2 += __shfl_xor_sync(0xffffffffu, s2, off);
    }
    if (lane == 0) { g_ssrc[gw] = s1; g_sdst[gw] = s2; }
}

// ---------------- per-node softmax aggregation (warp per dst node) ----------------
__global__ void k_agg(const float* __restrict__ bias, int relu) {
    int node = (blockIdx.x * blockDim.x + threadIdx.x) >> 5;
    int lane = threadIdx.x & 31;
    if (node >= N_NODES) return;

    const int beg = g_off[node];
    const int end = g_off[node + 1];
    const float sd = g_sdst[node];

    // pass 1: max of leaky_relu(s_src + s_dst)
    float m = -1e30f;
    for (int e = beg; e < end; e++) {
        float t = g_ssrc[g_csrc[e]] + sd;
        t = (t > 0.f) ? t : NEG_SLOPE * t;
        m = fmaxf(m, t);
    }
    // pass 2: unnormalized weighted sum + denom
    float4 acc = make_float4(0.f, 0.f, 0.f, 0.f);
    float den = 0.f;
    const float4* hw4 = (const float4*)g_hw;
    for (int e = beg; e < end; e++) {
        int src = g_csrc[e];
        float t = g_ssrc[src] + sd;
        t = (t > 0.f) ? t : NEG_SLOPE * t;
        float w = __expf(t - m);
        den += w;
        float4 v = hw4[src * 32 + lane];
        acc.x += w * v.x; acc.y += w * v.y; acc.z += w * v.z; acc.w += w * v.w;
    }
    float inv = 1.f / den;
    float4 b = ((const float4*)bias)[lane];
    float4 o;
    o.x = acc.x * inv + b.x; o.y = acc.y * inv + b.y;
    o.z = acc.z * inv + b.z; o.w = acc.w * inv + b.w;
    if (relu) {
        o.x = fmaxf(o.x, 0.f); o.y = fmaxf(o.y, 0.f);
        o.z = fmaxf(o.z, 0.f); o.w = fmaxf(o.w, 0.f);
    }
    ((float4*)g_h)[node * 32 + lane] = o;
}

// ---------------- pooling ----------------
__global__ void k_gbounds(const int* __restrict__ batch) {
    int g = threadIdx.x;
    if (g > N_GRAPHS) return;
    int lo = 0, hi = N_NODES;
    while (lo < hi) {
        int mid = (lo + hi) >> 1;
        if (batch[mid] < g) lo = mid + 1; else hi = mid;
    }
    g_gstart[g] = lo;
}

__global__ void k_pool() {
    int g = blockIdx.x;     // 64 graphs
    int c = threadIdx.x;    // 128 channels
    int s = g_gstart[g], e = g_gstart[g + 1];
    float a0 = 0.f, a1 = 0.f, a2 = 0.f, a3 = 0.f;
    int i = s;
    for (; i + 3 < e; i += 4) {
        a0 += g_h[(i + 0) * HID + c];
        a1 += g_h[(i + 1) * HID + c];
        a2 += g_h[(i + 2) * HID + c];
        a3 += g_h[(i + 3) * HID + c];
    }
    for (; i < e; i++) a0 += g_h[i * HID + c];
    float cnt = (float)(e - s);
    g_pool[g * HID + c] = (a0 + a1 + a2 + a3) / fmaxf(cnt, 1.f);
}

__global__ void k_final(const float* __restrict__ Wout, const float* __restrict__ bout,
                        float* __restrict__ out) {
    int g = blockIdx.x;     // 64
    int o = threadIdx.x;    // 64
    float acc = 0.f;
#pragma unroll 4
    for (int c = 0; c < HID; c++)
        acc += g_pool[g * HID + c] * Wout[c * OUT_CH + o];
    out[g * OUT_CH + o] = acc + bout[o];
}

// ---------------- launch ----------------
extern "C" void kernel_launch(void* const* d_in, const int* in_sizes, int n_in,
                              void* d_out, int out_size) {
    const int*   x     = (const int*)  d_in[0];
    const int*   ei    = (const int*)  d_in[1];
    const int*   batch = (const int*)  d_in[2];
    const float* emb   = (const float*)d_in[3];
    const float* Ws    = (const float*)d_in[4];
    const float* asrc  = (const float*)d_in[5];
    const float* adst  = (const float*)d_in[6];
    const float* bs    = (const float*)d_in[7];
    const float* Wout  = (const float*)d_in[8];
    const float* bout  = (const float*)d_in[9];
    float* out = (float*)d_out;

    const int* src = ei;            // edge_index[0]
    const int* dst = ei + N_EDGES;  // edge_index[1]

    cudaFuncSetAttribute(k_gemm, cudaFuncAttributeMaxDynamicSharedMemorySize, GEMM_SMEM);

    // CSR build
    k_zero<<<(N_NODES + 255) / 256, 256>>>();
    k_hist<<<1024, 256>>>(dst);
    k_scan<<<1, 1024>>>();
    k_fillcsr<<<1024, 256>>>(src, dst);

    // embedding
    k_embed<<<(N_NODES * 32 + 255) / 256, 256>>>(x, emb);

    // 3 GAT layers
    const int gemm_blocks = (N_NODES + 63) / 64;
    const int warp_blocks = (N_NODES * 32 + 255) / 256;
    for (int l = 0; l < 3; l++) {
        k_gemm<<<gemm_blocks, 256, GEMM_SMEM>>>(Ws + l * HID * HID);
        k_scores<<<warp_blocks, 256>>>(asrc + l * HID, adst + l * HID);
        k_agg<<<warp_blocks, 256>>>(bs + l * HID, (l < 2) ? 1 : 0);
    }

    // pooling + projection
    k_gbounds<<<1, 128>>>(batch);
    k_pool<<<N_GRAPHS, HID>>>();
    k_final<<<N_GRAPHS, OUT_CH>>>(Wout, bout, out);
}